// round 9
// baseline (speedup 1.0000x reference)
#include <cuda_runtime.h>
#include <cuda_bf16.h>

#define MAX_M 600000          // corners
#define EPSF 1e-8f
#define WSCALE 0.99f

typedef unsigned long long u64;

// Scratch (no cudaMalloc allowed). Zero-init at load = valid empty state;
// k_world resets every touched slot to 0 so graph replays stay deterministic.
__device__ u64    g_win64[MAX_M];   // [k+1 : 22b][px:9][py:9][pz:9]; 0 = empty
__device__ float4 g_ws[MAX_M];      // (world.x, world.y, world.z, sdf)

// fast tanh: (e^{2x}-1)/(e^{2x}+1), |err| ~1e-6 rel — fine vs 1e-3 gate
__device__ __forceinline__ float ftanh(float x) {
    float xc = fminf(fmaxf(x, -15.f), 15.f);
    float t = __expf(2.f * xc);
    return (t - 1.f) / (t + 1.f);
}

// ---------------------------------------------------------------------------
// Kernel 1: packed scatter. One thread per cube: coalesced cube_idx (32B) +
// vox (12B) reads, 8 x 64-bit atomicMax. Payload = (k+1)<<27 | px<<18|py<<9|pz.
// max-by-payload == max-by-k (JAX last-write-wins), and the winner's corner
// position rides along — k_world needs no gather afterwards.
// ---------------------------------------------------------------------------
__global__ void k_scatter(const int4* __restrict__ cube_idx,
                          const int*  __restrict__ vox,
                          int N, int M) {
    int i = blockIdx.x * blockDim.x + threadIdx.x;
    if (i >= N) return;
    int4 a = cube_idx[2 * i], b = cube_idx[2 * i + 1];
    int ji[8] = {a.x, a.y, a.z, a.w, b.x, b.y, b.z, b.w};
    int vx = vox[3 * i], vy = vox[3 * i + 1], vz = vox[3 * i + 2];
    u64 kbase = ((u64)(8 * i + 1)) << 27;
#pragma unroll
    for (int c = 0; c < 8; c++) {
        int j = ji[c];
        if (j < 0) j = 0;
        if (j >= M) j = M - 1;
        u64 pay = (kbase + ((u64)c << 27))
                | ((u64)(vx + (c & 1)) << 18)
                | ((u64)(vy + ((c >> 1) & 1)) << 9)
                |  (u64)(vz + ((c >> 2) & 1));
        atomicMax(&g_win64[j], pay);
    }
}

// ---------------------------------------------------------------------------
// Kernel 2: fully coalesced. g_ws[j] = (world.xyz, sdf[j]);
// world = corner_pos * (2/res) - 1 + deform. Resets winner slot to 0.
// ---------------------------------------------------------------------------
__global__ void k_world(const float* __restrict__ deform,
                        const float* __restrict__ sdf,
                        int M, float scale) {
    int j = blockIdx.x * blockDim.x + threadIdx.x;
    if (j >= M) return;
    u64 w = g_win64[j];
    g_win64[j] = 0ULL;                 // restore empty state for next replay
    float px = 0.f, py = 0.f, pz = 0.f;
    if (w != 0ULL) {
        px = (float)((int)(w >> 18) & 0x1FF);
        py = (float)((int)(w >> 9)  & 0x1FF);
        pz = (float)((int)w         & 0x1FF);
    }
    float4 ws;
    ws.x = px * scale - 1.f + deform[j * 3 + 0];
    ws.y = py * scale - 1.f + deform[j * 3 + 1];
    ws.z = pz * scale - 1.f + deform[j * 3 + 2];
    ws.w = sdf[j];
    g_ws[j] = ws;
}

// ---------------------------------------------------------------------------
// Kernel 3: per-cube dual-contouring math. One thread per cube, 256/block
// (best measured config). Outputs (flat concat, float32):
// [vertices 3N][L_dev 12N][p_alpha 3N][n_out 3N]
// ---------------------------------------------------------------------------
__global__ void __launch_bounds__(256)
k_main(const int* __restrict__ cube_idx,
       const float* __restrict__ alpha,
       const float* __restrict__ beta,
       float* __restrict__ out, int N) {
    int i = blockIdx.x * blockDim.x + threadIdx.x;
    if (i >= N) return;

    // --- corner indices (coalesced int4 loads) ---
    const int4* cp = (const int4*)(cube_idx + (size_t)i * 8);
    int4 ca = cp[0], cb = cp[1];
    int ci[8] = {ca.x, ca.y, ca.z, ca.w, cb.x, cb.y, cb.z, cb.w};

    // --- one LDG.128 gather per corner: world.xyz + sdf ---
    float s[8], wx[8], wy[8], wz[8];
    bool anyp = false, anyn = false;
#pragma unroll
    for (int c = 0; c < 8; c++) {
        float4 w = __ldg(&g_ws[ci[c]]);
        wx[c] = w.x; wy[c] = w.y; wz[c] = w.z;
        s[c] = w.w;
        anyp |= (w.w > 0.f);
        anyn |= !(w.w > 0.f);
    }
    bool surf = anyp && anyn;

    // --- normalized weights (vectorized loads) ---
    const float4* ap = (const float4*)(alpha + (size_t)i * 8);
    float4 av0 = ap[0], av1 = ap[1];
    float aarr[8] = {av0.x, av0.y, av0.z, av0.w, av1.x, av1.y, av1.z, av1.w};
    float an[8];
#pragma unroll
    for (int c = 0; c < 8; c++) an[c] = ftanh(aarr[c]) * WSCALE + 1.f;

    const float4* bp = (const float4*)(beta + (size_t)i * 12);
    float4 bv0 = bp[0], bv1 = bp[1], bv2 = bp[2];
    float barr[12] = {bv0.x, bv0.y, bv0.z, bv0.w, bv1.x, bv1.y, bv1.z, bv1.w,
                      bv2.x, bv2.y, bv2.z, bv2.w};
    float bn[12];
#pragma unroll
    for (int e = 0; e < 12; e++) bn[e] = ftanh(barr[e]) * WSCALE + 1.f;

    const int E0[12] = {0, 1, 4, 0, 2, 3, 6, 2, 2, 3, 7, 6};
    const int E1[12] = {1, 5, 5, 4, 3, 7, 7, 6, 0, 1, 5, 4};

    // --- single pass: ue (kept in regs), wbe, vd / n_alpha accum ---
    float uex[12], uey[12], uez[12], wbe[12];
    float wsum = 0.f;
    float vdx = 0.f, vdy = 0.f, vdz = 0.f;
    float nax = 0.f, nay = 0.f, naz = 0.f;
#pragma unroll
    for (int e = 0; e < 12; e++) {
        int c0 = E0[e], c1 = E1[e];
        float s0 = s[c0], s1 = s[c1];
        bool cr = ((s0 > 0.f) != (s1 > 0.f)) && surf;
        float wb = cr ? bn[e] : 0.f;
        wbe[e] = wb;
        wsum += wb;

        float w0 = an[c0] * fabsf(s0);
        float w1 = an[c1] * fabsf(s1);
        float invd = 1.f / (w0 + w1 + EPSF);
        float ux = (wx[c0] * w1 + wx[c1] * w0) * invd;
        float uy = (wy[c0] * w1 + wy[c1] * w0) * invd;
        float uz = (wz[c0] * w1 + wz[c1] * w0) * invd;
        uex[e] = ux; uey[e] = uy; uez[e] = uz;
        vdx += ux * wb; vdy += uy * wb; vdz += uz * wb;

        float evx = wx[c1] - wx[c0];
        float evy = wy[c1] - wy[c0];
        float evz = wz[c1] - wz[c0];
        float elen = sqrtf(evx * evx + evy * evy + evz * evz) + EPSF;
        float ds = s1 - s0;
        float sg = (ds > 0.f) ? 1.f : ((ds < 0.f) ? -1.f : 0.f);
        float f = sg / elen * wb;
        nax += evx * f; nay += evy * f; naz += evz * f;
    }

    float invw = 1.f / (wsum + EPSF);
    vdx *= invw; vdy *= invw; vdz *= invw;
    nax *= invw; nay *= invw; naz *= invw;
    float nn = sqrtf(nax * nax + nay * nay + naz * naz) + EPSF;
    float innn = 1.f / nn;
    nax *= innn; nay *= innn; naz *= innn;

    // --- distances to vd ---
    float dist[12];
    float sumd = 0.f, ne = 0.f;
#pragma unroll
    for (int e = 0; e < 12; e++) {
        float cmf = (wbe[e] > 0.f) ? 1.f : 0.f;   // bn >= 0.01, so wbe>0 <=> cross
        float dx = uex[e] - vdx;
        float dy = uey[e] - vdy;
        float dz = uez[e] - vdz;
        float d = sqrtf(dx * dx + dy * dy + dz * dz) * cmf;
        dist[e] = d;
        sumd += d;
        ne += cmf;
    }
    float mean = sumd / (ne + EPSF);

    // --- outputs ---
    float sm = surf ? 1.f : 0.f;
    size_t Ns = (size_t)N;
    float* vout = out;                 // vertices: 3N
    float* ldev = out + 3 * Ns;        // L_dev:   12N
    float* pout = out + 15 * Ns;       // p_alpha:  3N
    float* nout = out + 18 * Ns;       // n_out:    3N

    float vx = vdx * sm, vy = vdy * sm, vz = vdz * sm;
    vout[i * 3 + 0] = vx; vout[i * 3 + 1] = vy; vout[i * 3 + 2] = vz;
    pout[i * 3 + 0] = vx; pout[i * 3 + 1] = vy; pout[i * 3 + 2] = vz;
    nout[i * 3 + 0] = nax * sm; nout[i * 3 + 1] = nay * sm; nout[i * 3 + 2] = naz * sm;

    float ld[12];
#pragma unroll
    for (int e = 0; e < 12; e++) {
        float cmf = (wbe[e] > 0.f) ? 1.f : 0.f;
        ld[e] = fabsf(dist[e] - mean) * cmf;
    }
    float4* lp = (float4*)(ldev + (size_t)i * 12);
    lp[0] = make_float4(ld[0], ld[1], ld[2], ld[3]);
    lp[1] = make_float4(ld[4], ld[5], ld[6], ld[7]);
    lp[2] = make_float4(ld[8], ld[9], ld[10], ld[11]);
}

// ---------------------------------------------------------------------------
extern "C" void kernel_launch(void* const* d_in, const int* in_sizes, int n_in,
                              void* d_out, int out_size) {
    int N = in_sizes[0] / 3;
    int M = in_sizes[1];
    int base = (n_in >= 8 && in_sizes[3] == 1) ? 4 : 3;

    const int*   vox    = (const int*)d_in[0];
    const float* sdf    = (const float*)d_in[1];
    const int*   cidx   = (const int*)d_in[2];
    const float* deform = (const float*)d_in[base + 0];
    const float* beta   = (const float*)d_in[base + 1];
    const float* alpha  = (const float*)d_in[base + 2];
    float* out = (float*)d_out;

    const float scale = 2.0f / 256.0f;

    k_scatter<<<(N + 255) / 256, 256>>>((const int4*)cidx, vox, N, M);
    k_world  <<<(M + 255) / 256, 256>>>(deform, sdf, M, scale);
    k_main   <<<(N + 255) / 256, 256>>>(cidx, alpha, beta, out, N);
}

// round 11
// speedup vs baseline: 1.5192x; 1.5192x over previous
#include <cuda_runtime.h>
#include <cuda_bf16.h>

#define MAX_M 600000          // corners
#define EPSF 1e-8f
#define WSCALE 0.99f

// Scratch (no cudaMalloc allowed). Zero-init at load = valid empty state;
// k_world resets every touched slot to 0 so graph replays stay deterministic.
__device__ int    g_winner[MAX_M];   // (last flat writer index)+1 ; 0 = empty
__device__ float4 g_ws[MAX_M];       // (world.x, world.y, world.z, sdf)

// fast tanh: (e^{2x}-1)/(e^{2x}+1), |err| ~1e-6 rel — fine vs 1e-3 gate
__device__ __forceinline__ float ftanh(float x) {
    float xc = fminf(fmaxf(x, -15.f), 15.f);
    float t = __expf(2.f * xc);
    return (t - 1.f) / (t + 1.f);
}

// ---------------------------------------------------------------------------
// Kernel 1: winner = max flat index writing each slot (== JAX last-write-wins
// scatter). 32-bit atomics (64-bit packing measured slower). Stores k+1 so the
// zero-initialized buffer means "empty".
// ---------------------------------------------------------------------------
__global__ void k_scatter(const int4* __restrict__ cube_idx, int total4, int M) {
    int t = blockIdx.x * blockDim.x + threadIdx.x;
    if (t >= total4) return;
    int4 v = cube_idx[t];
    int k = t * 4;
    int j;
    j = v.x; if (j < 0) j = 0; if (j >= M) j = M - 1; atomicMax(&g_winner[j], k + 1);
    j = v.y; if (j < 0) j = 0; if (j >= M) j = M - 1; atomicMax(&g_winner[j], k + 2);
    j = v.z; if (j < 0) j = 0; if (j >= M) j = M - 1; atomicMax(&g_winner[j], k + 3);
    j = v.w; if (j < 0) j = 0; if (j >= M) j = M - 1; atomicMax(&g_winner[j], k + 4);
}

// ---------------------------------------------------------------------------
// Kernel 2: g_ws[j] = (world.xyz, sdf[j]); resets g_winner[j] = 0.
// world = (vox[winner/8] + corner(winner&7)) * (2/res) - 1 + deform.
// ---------------------------------------------------------------------------
__global__ void k_world(const int* __restrict__ vox,
                        const float* __restrict__ deform,
                        const float* __restrict__ sdf,
                        int M, float scale) {
    int j = blockIdx.x * blockDim.x + threadIdx.x;
    if (j >= M) return;
    int w = g_winner[j];
    g_winner[j] = 0;                   // restore empty state for next replay
    float px = 0.f, py = 0.f, pz = 0.f;
    if (w > 0) {
        int k = w - 1;
        int i = k >> 3, c = k & 7;
        px = (float)vox[i * 3 + 0] + (float)(c & 1);
        py = (float)vox[i * 3 + 1] + (float)((c >> 1) & 1);
        pz = (float)vox[i * 3 + 2] + (float)((c >> 2) & 1);
    }
    float4 ws;
    ws.x = px * scale - 1.f + deform[j * 3 + 0];
    ws.y = py * scale - 1.f + deform[j * 3 + 1];
    ws.z = pz * scale - 1.f + deform[j * 3 + 2];
    ws.w = sdf[j];
    g_ws[j] = ws;
}

// ---------------------------------------------------------------------------
// Kernel 3: per-cube dual-contouring math, register-dieted for occupancy:
// no stored ue[] (recomputed in pass 2), cross flags in a bitmask, bn folded
// into pass 1. __launch_bounds__(256,3) -> <=85 regs -> 24 warps/SM.
// Outputs (flat concat): [vertices 3N][L_dev 12N][p_alpha 3N][n_out 3N]
// ---------------------------------------------------------------------------
__global__ void __launch_bounds__(256, 3)
k_main(const int* __restrict__ cube_idx,
       const float* __restrict__ alpha,
       const float* __restrict__ beta,
       float* __restrict__ out, int N) {
    int i = blockIdx.x * blockDim.x + threadIdx.x;
    if (i >= N) return;

    // --- corner indices (coalesced int4 loads) ---
    const int4* cp = (const int4*)(cube_idx + (size_t)i * 8);
    int4 ca = cp[0], cb = cp[1];
    int ci[8] = {ca.x, ca.y, ca.z, ca.w, cb.x, cb.y, cb.z, cb.w};

    // --- one LDG.128 gather per corner: world.xyz + sdf ---
    float s[8], wx[8], wy[8], wz[8];
    bool anyp = false, anyn = false;
#pragma unroll
    for (int c = 0; c < 8; c++) {
        float4 w = __ldg(&g_ws[ci[c]]);
        wx[c] = w.x; wy[c] = w.y; wz[c] = w.z;
        s[c] = w.w;
        anyp |= (w.w > 0.f);
        anyn |= !(w.w > 0.f);
    }
    bool surf = anyp && anyn;

    // --- alpha weights ---
    const float4* ap = (const float4*)(alpha + (size_t)i * 8);
    float4 av0 = ap[0], av1 = ap[1];
    float aarr[8] = {av0.x, av0.y, av0.z, av0.w, av1.x, av1.y, av1.z, av1.w};
    float an[8];
#pragma unroll
    for (int c = 0; c < 8; c++) an[c] = ftanh(aarr[c]) * WSCALE + 1.f;

    // --- beta (tanh folded into pass 1; barr dies after it) ---
    const float4* bp = (const float4*)(beta + (size_t)i * 12);
    float4 bv0 = bp[0], bv1 = bp[1], bv2 = bp[2];
    float barr[12] = {bv0.x, bv0.y, bv0.z, bv0.w, bv1.x, bv1.y, bv1.z, bv1.w,
                      bv2.x, bv2.y, bv2.z, bv2.w};

    const int E0[12] = {0, 1, 4, 0, 2, 3, 6, 2, 2, 3, 7, 6};
    const int E1[12] = {1, 5, 5, 4, 3, 7, 7, 6, 0, 1, 5, 4};

    // --- pass 1: wsum, vd and n_alpha accumulation; cross flags -> bitmask ---
    unsigned cmask = 0;
    float wsum = 0.f;
    float vdx = 0.f, vdy = 0.f, vdz = 0.f;
    float nax = 0.f, nay = 0.f, naz = 0.f;
#pragma unroll
    for (int e = 0; e < 12; e++) {
        int c0 = E0[e], c1 = E1[e];
        float s0 = s[c0], s1 = s[c1];
        bool cr = ((s0 > 0.f) != (s1 > 0.f)) && surf;
        cmask |= (cr ? 1u : 0u) << e;
        float wb = cr ? (ftanh(barr[e]) * WSCALE + 1.f) : 0.f;
        wsum += wb;

        float w0 = an[c0] * fabsf(s0);
        float w1 = an[c1] * fabsf(s1);
        float invd = 1.f / (w0 + w1 + EPSF);
        vdx += (wx[c0] * w1 + wx[c1] * w0) * invd * wb;
        vdy += (wy[c0] * w1 + wy[c1] * w0) * invd * wb;
        vdz += (wz[c0] * w1 + wz[c1] * w0) * invd * wb;

        float evx = wx[c1] - wx[c0];
        float evy = wy[c1] - wy[c0];
        float evz = wz[c1] - wz[c0];
        float elen = sqrtf(evx * evx + evy * evy + evz * evz) + EPSF;
        float ds = s1 - s0;
        float sg = (ds > 0.f) ? 1.f : ((ds < 0.f) ? -1.f : 0.f);
        float f = sg / elen * wb;
        nax += evx * f; nay += evy * f; naz += evz * f;
    }

    float invw = 1.f / (wsum + EPSF);
    vdx *= invw; vdy *= invw; vdz *= invw;
    nax *= invw; nay *= invw; naz *= invw;
    float nn = sqrtf(nax * nax + nay * nay + naz * naz) + EPSF;
    float innn = 1.f / nn;
    nax *= innn; nay *= innn; naz *= innn;

    // --- pass 2: recompute ue, distances to vd ---
    float dist[12];
    float sumd = 0.f, ne = 0.f;
#pragma unroll
    for (int e = 0; e < 12; e++) {
        int c0 = E0[e], c1 = E1[e];
        float s0 = s[c0], s1 = s[c1];
        float cmf = (cmask >> e) & 1u ? 1.f : 0.f;
        float w0 = an[c0] * fabsf(s0);
        float w1 = an[c1] * fabsf(s1);
        float invd = 1.f / (w0 + w1 + EPSF);
        float dx = (wx[c0] * w1 + wx[c1] * w0) * invd - vdx;
        float dy = (wy[c0] * w1 + wy[c1] * w0) * invd - vdy;
        float dz = (wz[c0] * w1 + wz[c1] * w0) * invd - vdz;
        float d = sqrtf(dx * dx + dy * dy + dz * dz) * cmf;
        dist[e] = d;
        sumd += d;
        ne += cmf;
    }
    float mean = sumd / (ne + EPSF);

    // --- outputs ---
    float sm = surf ? 1.f : 0.f;
    size_t Ns = (size_t)N;
    float* vout = out;                 // vertices: 3N
    float* ldev = out + 3 * Ns;        // L_dev:   12N
    float* pout = out + 15 * Ns;       // p_alpha:  3N
    float* nout = out + 18 * Ns;       // n_out:    3N

    float vx = vdx * sm, vy = vdy * sm, vz = vdz * sm;
    vout[i * 3 + 0] = vx; vout[i * 3 + 1] = vy; vout[i * 3 + 2] = vz;
    pout[i * 3 + 0] = vx; pout[i * 3 + 1] = vy; pout[i * 3 + 2] = vz;
    nout[i * 3 + 0] = nax * sm; nout[i * 3 + 1] = nay * sm; nout[i * 3 + 2] = naz * sm;

    float ld[12];
#pragma unroll
    for (int e = 0; e < 12; e++) {
        float cmf = (cmask >> e) & 1u ? 1.f : 0.f;
        ld[e] = fabsf(dist[e] - mean) * cmf;
    }
    float4* lp = (float4*)(ldev + (size_t)i * 12);
    lp[0] = make_float4(ld[0], ld[1], ld[2], ld[3]);
    lp[1] = make_float4(ld[4], ld[5], ld[6], ld[7]);
    lp[2] = make_float4(ld[8], ld[9], ld[10], ld[11]);
}

// ---------------------------------------------------------------------------
extern "C" void kernel_launch(void* const* d_in, const int* in_sizes, int n_in,
                              void* d_out, int out_size) {
    int N = in_sizes[0] / 3;
    int M = in_sizes[1];
    int base = (n_in >= 8 && in_sizes[3] == 1) ? 4 : 3;

    const int*   vox    = (const int*)d_in[0];
    const float* sdf    = (const float*)d_in[1];
    const int*   cidx   = (const int*)d_in[2];
    const float* deform = (const float*)d_in[base + 0];
    const float* beta   = (const float*)d_in[base + 1];
    const float* alpha  = (const float*)d_in[base + 2];
    float* out = (float*)d_out;

    int total4 = N * 2;                  // N*8 indices / 4 per thread
    const float scale = 2.0f / 256.0f;

    k_scatter<<<(total4 + 255) / 256, 256>>>((const int4*)cidx, total4, M);
    k_world  <<<(M + 255) / 256, 256>>>(vox, deform, sdf, M, scale);
    k_main   <<<(N + 255) / 256, 256>>>(cidx, alpha, beta, out, N);
}

// round 12
// speedup vs baseline: 1.8106x; 1.1918x over previous
#include <cuda_runtime.h>
#include <cuda_bf16.h>

#define MAX_M 600000          // corners
#define EPSF 1e-8f
#define WSCALE 0.99f

// Scratch (no cudaMalloc allowed). Zero-init at load = valid empty state;
// k_world resets every touched slot to 0 so graph replays stay deterministic.
__device__ int    g_winner[MAX_M];   // (last flat writer index)+1 ; 0 = empty
__device__ float4 g_ws[MAX_M];       // (world.x, world.y, world.z, sdf)

// --- HW approx ops (sm_75+): 1 MUFU each ---
__device__ __forceinline__ float fast_rcp(float x)   { float r; asm("rcp.approx.f32 %0,%1;"   : "=f"(r) : "f"(x)); return r; }
__device__ __forceinline__ float fast_rsqrt(float x) { float r; asm("rsqrt.approx.f32 %0,%1;" : "=f"(r) : "f"(x)); return r; }
__device__ __forceinline__ float fast_sqrt(float x)  { float r; asm("sqrt.approx.f32 %0,%1;"  : "=f"(r) : "f"(x)); return r; }
__device__ __forceinline__ float fast_tanh(float x)  { float r; asm("tanh.approx.f32 %0,%1;"  : "=f"(r) : "f"(x)); return r; }

// ---------------------------------------------------------------------------
// Kernel 1: winner = max flat index writing each slot (== JAX last-write-wins
// scatter). 32-bit atomics (64-bit packing measured slower). Stores k+1 so the
// zero-initialized buffer means "empty".
// ---------------------------------------------------------------------------
__global__ void k_scatter(const int4* __restrict__ cube_idx, int total4, int M) {
    int t = blockIdx.x * blockDim.x + threadIdx.x;
    if (t >= total4) return;
    int4 v = cube_idx[t];
    int k = t * 4;
    int j;
    j = v.x; if (j < 0) j = 0; if (j >= M) j = M - 1; atomicMax(&g_winner[j], k + 1);
    j = v.y; if (j < 0) j = 0; if (j >= M) j = M - 1; atomicMax(&g_winner[j], k + 2);
    j = v.z; if (j < 0) j = 0; if (j >= M) j = M - 1; atomicMax(&g_winner[j], k + 3);
    j = v.w; if (j < 0) j = 0; if (j >= M) j = M - 1; atomicMax(&g_winner[j], k + 4);
}

// ---------------------------------------------------------------------------
// Kernel 2: g_ws[j] = (world.xyz, sdf[j]); resets g_winner[j] = 0.
// world = (vox[winner/8] + corner(winner&7)) * (2/res) - 1 + deform.
// ---------------------------------------------------------------------------
__global__ void k_world(const int* __restrict__ vox,
                        const float* __restrict__ deform,
                        const float* __restrict__ sdf,
                        int M, float scale) {
    int j = blockIdx.x * blockDim.x + threadIdx.x;
    if (j >= M) return;
    int w = g_winner[j];
    g_winner[j] = 0;                   // restore empty state for next replay
    float px = 0.f, py = 0.f, pz = 0.f;
    if (w > 0) {
        int k = w - 1;
        int i = k >> 3, c = k & 7;
        px = (float)vox[i * 3 + 0] + (float)(c & 1);
        py = (float)vox[i * 3 + 1] + (float)((c >> 1) & 1);
        pz = (float)vox[i * 3 + 2] + (float)((c >> 2) & 1);
    }
    float4 ws;
    ws.x = px * scale - 1.f + deform[j * 3 + 0];
    ws.y = py * scale - 1.f + deform[j * 3 + 1];
    ws.z = pz * scale - 1.f + deform[j * 3 + 2];
    ws.w = sdf[j];
    g_ws[j] = ws;
}

// ---------------------------------------------------------------------------
// Kernel 3: per-cube dual-contouring math, instruction-dieted with HW approx
// ops (tanh/rcp/rsqrt/sqrt .approx). One thread per cube, 256/block.
// Outputs (flat concat): [vertices 3N][L_dev 12N][p_alpha 3N][n_out 3N]
// ---------------------------------------------------------------------------
__global__ void __launch_bounds__(256)
k_main(const int* __restrict__ cube_idx,
       const float* __restrict__ alpha,
       const float* __restrict__ beta,
       float* __restrict__ out, int N) {
    int i = blockIdx.x * blockDim.x + threadIdx.x;
    if (i >= N) return;

    // --- corner indices (coalesced int4 loads) ---
    const int4* cp = (const int4*)(cube_idx + (size_t)i * 8);
    int4 ca = cp[0], cb = cp[1];
    int ci[8] = {ca.x, ca.y, ca.z, ca.w, cb.x, cb.y, cb.z, cb.w};

    // --- one LDG.128 gather per corner: world.xyz + sdf ---
    float s[8], wx[8], wy[8], wz[8];
    bool anyp = false, anyn = false;
#pragma unroll
    for (int c = 0; c < 8; c++) {
        float4 w = __ldg(&g_ws[ci[c]]);
        wx[c] = w.x; wy[c] = w.y; wz[c] = w.z;
        s[c] = w.w;
        anyp |= (w.w > 0.f);
        anyn |= !(w.w > 0.f);
    }
    bool surf = anyp && anyn;

    // --- alpha weights (HW tanh) ---
    const float4* ap = (const float4*)(alpha + (size_t)i * 8);
    float4 av0 = ap[0], av1 = ap[1];
    float aarr[8] = {av0.x, av0.y, av0.z, av0.w, av1.x, av1.y, av1.z, av1.w};
    float an[8];
#pragma unroll
    for (int c = 0; c < 8; c++) an[c] = fast_tanh(aarr[c]) * WSCALE + 1.f;

    const float4* bp = (const float4*)(beta + (size_t)i * 12);
    float4 bv0 = bp[0], bv1 = bp[1], bv2 = bp[2];
    float barr[12] = {bv0.x, bv0.y, bv0.z, bv0.w, bv1.x, bv1.y, bv1.z, bv1.w,
                      bv2.x, bv2.y, bv2.z, bv2.w};

    const int E0[12] = {0, 1, 4, 0, 2, 3, 6, 2, 2, 3, 7, 6};
    const int E1[12] = {1, 5, 5, 4, 3, 7, 7, 6, 0, 1, 5, 4};

    // --- pass 1: wsum, vd and n_alpha accumulation; cross flags -> bitmask ---
    unsigned cmask = 0;
    float wsum = 0.f;
    float vdx = 0.f, vdy = 0.f, vdz = 0.f;
    float nax = 0.f, nay = 0.f, naz = 0.f;
#pragma unroll
    for (int e = 0; e < 12; e++) {
        int c0 = E0[e], c1 = E1[e];
        float s0 = s[c0], s1 = s[c1];
        bool cr = ((s0 > 0.f) != (s1 > 0.f)) && surf;
        cmask |= (cr ? 1u : 0u) << e;
        float wb = cr ? (fast_tanh(barr[e]) * WSCALE + 1.f) : 0.f;
        wsum += wb;

        float w0 = an[c0] * fabsf(s0);
        float w1 = an[c1] * fabsf(s1);
        float t = wb * fast_rcp(w0 + w1 + EPSF);
        vdx += (wx[c0] * w1 + wx[c1] * w0) * t;
        vdy += (wy[c0] * w1 + wy[c1] * w0) * t;
        vdz += (wz[c0] * w1 + wz[c1] * w0) * t;

        float evx = wx[c1] - wx[c0];
        float evy = wy[c1] - wy[c0];
        float evz = wz[c1] - wz[c0];
        float dot = evx * evx + evy * evy + evz * evz;
        // f = sign(s1-s0)/|ev| * wb ; +1e-30 keeps rsqrt finite so wb=0 kills it
        float f = copysignf(fast_rsqrt(dot + 1e-30f), s1 - s0) * wb;
        nax += evx * f; nay += evy * f; naz += evz * f;
    }

    float invw = fast_rcp(wsum + EPSF);
    vdx *= invw; vdy *= invw; vdz *= invw;
    nax *= invw; nay *= invw; naz *= invw;
    float innn = fast_rsqrt(nax * nax + nay * nay + naz * naz + 1e-30f);
    // match ref: n/(||n||+eps) ~= n*rsqrt(||n||^2) ; diff ~1e-8/||n|| — negligible
    nax *= innn; nay *= innn; naz *= innn;

    // --- pass 2: recompute ue, distances to vd ---
    float dist[12];
    float sumd = 0.f, ne = 0.f;
#pragma unroll
    for (int e = 0; e < 12; e++) {
        int c0 = E0[e], c1 = E1[e];
        float cmf = (cmask >> e) & 1u ? 1.f : 0.f;
        float w0 = an[c0] * fabsf(s[c0]);
        float w1 = an[c1] * fabsf(s[c1]);
        float invd = fast_rcp(w0 + w1 + EPSF);
        float dx = (wx[c0] * w1 + wx[c1] * w0) * invd - vdx;
        float dy = (wy[c0] * w1 + wy[c1] * w0) * invd - vdy;
        float dz = (wz[c0] * w1 + wz[c1] * w0) * invd - vdz;
        float d = fast_sqrt(dx * dx + dy * dy + dz * dz) * cmf;
        dist[e] = d;
        sumd += d;
        ne += cmf;
    }
    float mean = sumd * fast_rcp(ne + EPSF);

    // --- outputs ---
    float sm = surf ? 1.f : 0.f;
    size_t Ns = (size_t)N;
    float* vout = out;                 // vertices: 3N
    float* ldev = out + 3 * Ns;        // L_dev:   12N
    float* pout = out + 15 * Ns;       // p_alpha:  3N
    float* nout = out + 18 * Ns;       // n_out:    3N

    float vx = vdx * sm, vy = vdy * sm, vz = vdz * sm;
    vout[i * 3 + 0] = vx; vout[i * 3 + 1] = vy; vout[i * 3 + 2] = vz;
    pout[i * 3 + 0] = vx; pout[i * 3 + 1] = vy; pout[i * 3 + 2] = vz;
    nout[i * 3 + 0] = nax * sm; nout[i * 3 + 1] = nay * sm; nout[i * 3 + 2] = naz * sm;

    float ld[12];
#pragma unroll
    for (int e = 0; e < 12; e++) {
        float cmf = (cmask >> e) & 1u ? 1.f : 0.f;
        ld[e] = fabsf(dist[e] - mean) * cmf;
    }
    float4* lp = (float4*)(ldev + (size_t)i * 12);
    lp[0] = make_float4(ld[0], ld[1], ld[2], ld[3]);
    lp[1] = make_float4(ld[4], ld[5], ld[6], ld[7]);
    lp[2] = make_float4(ld[8], ld[9], ld[10], ld[11]);
}

// ---------------------------------------------------------------------------
extern "C" void kernel_launch(void* const* d_in, const int* in_sizes, int n_in,
                              void* d_out, int out_size) {
    int N = in_sizes[0] / 3;
    int M = in_sizes[1];
    int base = (n_in >= 8 && in_sizes[3] == 1) ? 4 : 3;

    const int*   vox    = (const int*)d_in[0];
    const float* sdf    = (const float*)d_in[1];
    const int*   cidx   = (const int*)d_in[2];
    const float* deform = (const float*)d_in[base + 0];
    const float* beta   = (const float*)d_in[base + 1];
    const float* alpha  = (const float*)d_in[base + 2];
    float* out = (float*)d_out;

    int total4 = N * 2;                  // N*8 indices / 4 per thread
    const float scale = 2.0f / 256.0f;

    k_scatter<<<(total4 + 255) / 256, 256>>>((const int4*)cidx, total4, M);
    k_world  <<<(M + 255) / 256, 256>>>(vox, deform, sdf, M, scale);
    k_main   <<<(N + 255) / 256, 256>>>(cidx, alpha, beta, out, N);
}